// round 16
// baseline (speedup 1.0000x reference)
#include <cuda_runtime.h>
#include <cuda_bf16.h>
#include <math.h>
#include <stdint.h>

#define B_SZ 2048
#define M_SZ 1024
#define D_SZ 64
#define KDIM 128
#define TILE_BYTES 32768

// ---------------- device scratch ----------------
__device__ float g_uacc[(size_t)B_SZ * KDIM];   // [b][T1|T2] atomically reduced over mb
__device__ float g_nacc[B_SZ];                  // norm, atomically reduced

// ---------------- helpers ----------------
__device__ __forceinline__ uint32_t smem_u32(const void* p) {
    uint32_t a;
    asm("{ .reg .u64 t; cvta.to.shared.u64 t, %1; cvt.u32.u64 %0, t; }" : "=r"(a) : "l"(p));
    return a;
}
// byte offset of element (r, c) inside a swizzled 128x128 bf16 tile
__device__ __forceinline__ uint32_t tile_off(int r, int c) {
    int ch = c >> 3;
    return (uint32_t)(r * 256 + (((ch ^ (r & 7))) << 4) + ((c & 7) << 1));
}
__device__ __forceinline__ void ldmx4(uint32_t* r, uint32_t addr) {
    asm volatile("ldmatrix.sync.aligned.m8n8.x4.shared.b16 {%0,%1,%2,%3}, [%4];"
        : "=r"(r[0]), "=r"(r[1]), "=r"(r[2]), "=r"(r[3]) : "r"(addr));
}
__device__ __forceinline__ void mma16816(float* c, const uint32_t* a, uint32_t b0, uint32_t b1) {
    asm volatile(
        "mma.sync.aligned.m16n8k16.row.col.f32.bf16.bf16.f32 "
        "{%0,%1,%2,%3}, {%4,%5,%6,%7}, {%8,%9}, {%0,%1,%2,%3};"
        : "+f"(c[0]), "+f"(c[1]), "+f"(c[2]), "+f"(c[3])
        : "r"(a[0]), "r"(a[1]), "r"(a[2]), "r"(a[3]), "r"(b0), "r"(b1));
}
__device__ __forceinline__ void split_bf(float v, __nv_bfloat16& h, __nv_bfloat16& l) {
    h = __float2bfloat16(v);
    l = __float2bfloat16(v - __bfloat162float(h));
}
union Pack8 { __nv_bfloat16 b[8]; uint4 v; };

// ================= warp-MMA core =================
// 512 threads = 16 warps, warp grid 4(m) x 4(n); warp tile 32 x 32.
// C ~= (Ah+Al)(Bh+Bl)^T with hh+hl+lh (ll dropped), K = 128.
__device__ __forceinline__ void gemm_core(float acc[2][4][4],
                                          uint32_t sAh, uint32_t sAl,
                                          uint32_t sBh, uint32_t sBl,
                                          int warp_m, int warp_n, int lane) {
    int s  = lane & 7;
    int q8 = (lane >> 3) & 1;
    int hi = lane >> 4;

    #pragma unroll
    for (int k = 0; k < 8; k++) {
        uint32_t cx = (uint32_t)(((2 * k + hi) ^ s) << 4);

        uint32_t ah[2][4], al[2][4], bh[2][4], bl[2][4];
        #pragma unroll
        for (int mi = 0; mi < 2; mi++) {
            int rA = warp_m * 32 + mi * 16 + s + (q8 << 3);
            uint32_t off = (uint32_t)(rA * 256) + cx;
            ldmx4(ah[mi], sAh + off);
            ldmx4(al[mi], sAl + off);
        }
        #pragma unroll
        for (int nt = 0; nt < 2; nt++) {
            int rB = warp_n * 32 + nt * 16 + s + (q8 << 3);
            uint32_t off = (uint32_t)(rB * 256) + cx;
            ldmx4(bh[nt], sBh + off);
            ldmx4(bl[nt], sBl + off);
        }

        #pragma unroll
        for (int mi = 0; mi < 2; mi++)
            #pragma unroll
            for (int nt = 0; nt < 2; nt++)
                #pragma unroll
                for (int sb = 0; sb < 2; sb++)
                    mma16816(acc[mi][nt * 2 + sb], ah[mi], bh[nt][sb], bh[nt][sb + 2]);
        #pragma unroll
        for (int mi = 0; mi < 2; mi++)
            #pragma unroll
            for (int nt = 0; nt < 2; nt++)
                #pragma unroll
                for (int sb = 0; sb < 2; sb++)
                    mma16816(acc[mi][nt * 2 + sb], ah[mi], bl[nt][sb], bl[nt][sb + 2]);
        #pragma unroll
        for (int mi = 0; mi < 2; mi++)
            #pragma unroll
            for (int nt = 0; nt < 2; nt++)
                #pragma unroll
                for (int sb = 0; sb < 2; sb++)
                    mma16816(acc[mi][nt * 2 + sb], al[mi], bh[nt][sb], bh[nt][sb + 2]);
    }
}

// ---------------- fused kernel: in-smem prep -> GEMM1 -> exp -> GEMM2 -> REDG ----------------
// grid (8 mb, 16 bb) = 128 CTAs, 512 threads, 192KB dyn smem.
// smem bufs: b0=Xh->Wh, b1=Xl->Wl, b2=Bmh, b3=Bml, b4=PTh, b5=PTl.
__global__ __launch_bounds__(512) void fused_mma(const float* __restrict__ X,
                                                 const float* __restrict__ Mu0,
                                                 const float* __restrict__ Mu1,
                                                 const float* __restrict__ S0,
                                                 const float* __restrict__ S1,
                                                 const float* __restrict__ Lam,
                                                 const float* __restrict__ tp,
                                                 const float* __restrict__ ep) {
    extern __shared__ char smem[];
    __shared__ float2 s_hl[128];
    __shared__ float  s_nsum[128];

    int tx = threadIdx.x, wid = tx >> 5, lane = tx & 31;
    int warp_m = wid & 3, warp_n = wid >> 2;
    int g = lane >> 2, t4 = lane & 3;
    int mb = blockIdx.x;
    int bb = blockIdx.y;
    int mcol0 = mb * 128;
    int brow0 = bb * 128;

    char* c0 = smem;
    char* c1 = smem + TILE_BYTES;
    char* c2 = smem + 2 * TILE_BYTES;
    char* c3 = smem + 3 * TILE_BYTES;
    char* c4 = smem + 4 * TILE_BYTES;
    char* c5 = smem + 5 * TILE_BYTES;
    uint32_t b0 = smem_u32(c0), b1 = smem_u32(c1);
    uint32_t b2 = smem_u32(c2), b3 = smem_u32(c3);
    uint32_t b4 = smem_u32(c4), b5 = smem_u32(c5);

    if (tx < 128) s_nsum[tx] = 0.0f;

    // ======== prologue: compute param tiles (Bm, PT) and X tiles in smem ========
    {
        float t   = tp[0];
        float eps = ep[0];
        float eps2 = eps * eps;
        float eps4 = eps2 * eps2;
        float omt  = 1.0f - t;

        int m_local = tx >> 2;       // 0..127
        int dq = tx & 3;             // d quarter
        int m = mcol0 + m_local;
        uint32_t rowoffM = (uint32_t)(m_local * 256);
        float hsum = 0.0f;

        #pragma unroll
        for (int hh = 0; hh < 2; hh++) {
            int d0 = dq * 16 + hh * 8;
            Pack8 invH, invL, m2H, m2L;
            float kk8[8], cc8[8];
            #pragma unroll
            for (int q = 0; q < 2; q++) {
                int idx = m * D_SZ + d0 + q * 4;
                float4 s0v  = *(const float4*)&S0[idx];
                float4 s1v  = *(const float4*)&S1[idx];
                float4 mu0v = *(const float4*)&Mu0[idx];
                float4 mu1v = *(const float4*)&Mu1[idx];
                const float* s0p = &s0v.x; const float* s1p = &s1v.x;
                const float* m0p = &mu0v.x; const float* m1p = &mu1v.x;
                #pragma unroll
                for (int e = 0; e < 4; e++) {
                    float s0 = s0p[e], s1 = s1p[e], mu0 = m0p[e], mu1 = m1p[e];
                    float Ds = sqrtf(4.0f * s0 * s1 + eps4);
                    float Cs = 0.5f * (Ds - eps2);
                    float mt = omt * mu0 + t * mu1;
                    float Sg = omt * omt * s0 + t * t * s1 + 2.0f * t * omt * (Cs + 0.5f * eps2);
                    float Pt = t * s1 + omt * Cs;
                    float Qt = omt * s0 + t * Cs;
                    float St = Pt - Qt - eps2 * t;
                    float inv = 1.0f / Sg;
                    float Kk  = St * inv;
                    float v   = mu1 - mu0;
                    float c   = v - Kk * mt;
                    int ei = q * 4 + e;
                    split_bf(inv, invH.b[ei], invL.b[ei]);
                    split_bf(-2.0f * mt * inv, m2H.b[ei], m2L.b[ei]);
                    kk8[ei] = Kk;
                    cc8[ei] = c;
                    hsum += mt * mt * inv + logf(Sg);
                }
            }
            // Bm tile stores (row m_local): chunk-aligned 16B
            uint32_t ch1 = (uint32_t)(((dq * 2 + hh) ^ (m_local & 7)) << 4);
            uint32_t ch2 = (uint32_t)(((8 + dq * 2 + hh) ^ (m_local & 7)) << 4);
            *(uint4*)(c2 + rowoffM + ch1) = invH.v;
            *(uint4*)(c3 + rowoffM + ch1) = invL.v;
            *(uint4*)(c2 + rowoffM + ch2) = m2H.v;
            *(uint4*)(c3 + rowoffM + ch2) = m2L.v;
            // PT tile stores (row d for Kk, row 64+d for c; col m_local): scalar
            #pragma unroll
            for (int e = 0; e < 8; e++) {
                int d = d0 + e;
                __nv_bfloat16 h, l;
                uint32_t o1 = tile_off(d, m_local);
                split_bf(kk8[e], h, l);
                *(__nv_bfloat16*)(c4 + o1) = h;
                *(__nv_bfloat16*)(c5 + o1) = l;
                uint32_t o2 = tile_off(D_SZ + d, m_local);
                split_bf(cc8[e], h, l);
                *(__nv_bfloat16*)(c4 + o2) = h;
                *(__nv_bfloat16*)(c5 + o2) = l;
            }
        }
        // reduce hsum over quad (4 threads share m_local)
        hsum += __shfl_xor_sync(0xFFFFFFFF, hsum, 1);
        hsum += __shfl_xor_sync(0xFFFFFFFF, hsum, 2);
        if ((tx & 3) == 0) s_hl[m_local] = make_float2(-0.5f * hsum, Lam[m]);

        // X tile: row = tx>>2 handles its d-quarter
        int row = tx >> 2;
        uint32_t rowoffB = (uint32_t)(row * 256);
        #pragma unroll
        for (int hh = 0; hh < 2; hh++) {
            int d0 = dq * 16 + hh * 8;
            Pack8 x2H, x2L, xH, xL;
            #pragma unroll
            for (int q = 0; q < 2; q++) {
                float4 xv = *(const float4*)&X[(brow0 + row) * D_SZ + d0 + q * 4];
                const float* xp = &xv.x;
                #pragma unroll
                for (int e = 0; e < 4; e++) {
                    int ei = q * 4 + e;
                    float x = xp[e];
                    split_bf(x * x, x2H.b[ei], x2L.b[ei]);
                    split_bf(x, xH.b[ei], xL.b[ei]);
                }
            }
            uint32_t ch1 = (uint32_t)(((dq * 2 + hh) ^ (row & 7)) << 4);
            uint32_t ch2 = (uint32_t)(((8 + dq * 2 + hh) ^ (row & 7)) << 4);
            *(uint4*)(c0 + rowoffB + ch1) = x2H.v;
            *(uint4*)(c1 + rowoffB + ch1) = x2L.v;
            *(uint4*)(c0 + rowoffB + ch2) = xH.v;
            *(uint4*)(c1 + rowoffB + ch2) = xL.v;
        }
    }
    __syncthreads();

    float acc[2][4][4];
    #pragma unroll
    for (int i = 0; i < 2; i++)
        #pragma unroll
        for (int j = 0; j < 4; j++)
            #pragma unroll
            for (int e = 0; e < 4; e++) acc[i][j][e] = 0.0f;

    // GEMM1: S = Xcat @ Bm^T
    gemm_core(acc, b0, b1, b2, b3, warp_m, warp_n, lane);

    __syncthreads();   // everyone done reading X and Bm before W overwrite

    // epilogue: exp -> W (hi/lo) into buf0/buf1 (swizzled), norm partials
    #pragma unroll
    for (int mi = 0; mi < 2; mi++) {
        int r0 = warp_m * 32 + mi * 16 + g;
        int r1 = r0 + 8;
        float ns0 = 0.0f, ns1 = 0.0f;
        #pragma unroll
        for (int n8 = 0; n8 < 4; n8++) {
            int ml = warp_n * 32 + n8 * 8 + t4 * 2;
            float2 hlA = s_hl[ml], hlB = s_hl[ml + 1];
            float* c = acc[mi][n8];

            float lw0 = fmaf(c[0], -0.5f, hlA.x); lw0 = fminf(fmaxf(lw0, -50.f), 50.f);
            float lw1 = fmaf(c[1], -0.5f, hlB.x); lw1 = fminf(fmaxf(lw1, -50.f), 50.f);
            float lw2 = fmaf(c[2], -0.5f, hlA.x); lw2 = fminf(fmaxf(lw2, -50.f), 50.f);
            float lw3 = fmaf(c[3], -0.5f, hlB.x); lw3 = fminf(fmaxf(lw3, -50.f), 50.f);
            float w0 = __expf(lw0) * hlA.y;
            float w1 = __expf(lw1) * hlB.y;
            float w2 = __expf(lw2) * hlA.y;
            float w3 = __expf(lw3) * hlB.y;
            ns0 += w0 + w1;
            ns1 += w2 + w3;

            __nv_bfloat16 h, l;
            __nv_bfloat162 ph, pl;
            split_bf(w0, h, l); ph.x = h; pl.x = l;
            split_bf(w1, h, l); ph.y = h; pl.y = l;
            uint32_t o0 = tile_off(r0, ml);
            *(__nv_bfloat162*)(c0 + o0) = ph;
            *(__nv_bfloat162*)(c1 + o0) = pl;
            split_bf(w2, h, l); ph.x = h; pl.x = l;
            split_bf(w3, h, l); ph.y = h; pl.y = l;
            uint32_t o1 = tile_off(r1, ml);
            *(__nv_bfloat162*)(c0 + o1) = ph;
            *(__nv_bfloat162*)(c1 + o1) = pl;
        }
        ns0 += __shfl_xor_sync(0xFFFFFFFF, ns0, 1);
        ns0 += __shfl_xor_sync(0xFFFFFFFF, ns0, 2);
        ns1 += __shfl_xor_sync(0xFFFFFFFF, ns1, 1);
        ns1 += __shfl_xor_sync(0xFFFFFFFF, ns1, 2);
        if (t4 == 0) {
            atomicAdd(&s_nsum[r0], ns0);
            atomicAdd(&s_nsum[r1], ns1);
        }
    }
    __syncthreads();   // W writes visible to all warps
    if (tx < 128) atomicAdd(&g_nacc[brow0 + tx], s_nsum[tx]);

    // GEMM2: u-partial = W @ PT^T (PT already resident in b4/b5)
    #pragma unroll
    for (int i = 0; i < 2; i++)
        #pragma unroll
        for (int j = 0; j < 4; j++)
            #pragma unroll
            for (int e = 0; e < 4; e++) acc[i][j][e] = 0.0f;

    gemm_core(acc, b0, b1, b4, b5, warp_m, warp_n, lane);

    #pragma unroll
    for (int mi = 0; mi < 2; mi++) {
        int r0 = brow0 + warp_m * 32 + mi * 16 + g;
        int r1 = r0 + 8;
        #pragma unroll
        for (int n8 = 0; n8 < 4; n8++) {
            int col = warp_n * 32 + n8 * 8 + t4 * 2;
            float* c = acc[mi][n8];
            atomicAdd(&g_uacc[(size_t)r0 * KDIM + col],     c[0]);
            atomicAdd(&g_uacc[(size_t)r0 * KDIM + col + 1], c[1]);
            atomicAdd(&g_uacc[(size_t)r1 * KDIM + col],     c[2]);
            atomicAdd(&g_uacc[(size_t)r1 * KDIM + col + 1], c[3]);
        }
    }
}

// ---------------- finalize ----------------
__global__ void finalize(const float* __restrict__ X, float* __restrict__ out) {
    int i = blockIdx.x * blockDim.x + threadIdx.x;
    int b = i >> 6, d = i & 63;
    float t1 = g_uacc[(size_t)b * KDIM + d];
    float t2 = g_uacc[(size_t)b * KDIM + D_SZ + d];
    float nr = g_nacc[b];
    out[i] = (X[i] * t1 + t2) / nr;
}

// ---------------- launch ----------------
#define DYN_SMEM (6 * TILE_BYTES)   // 192KB

extern "C" void kernel_launch(void* const* d_in, const int* in_sizes, int n_in,
                              void* d_out, int out_size) {
    const float* X   = (const float*)d_in[0];
    const float* Mu0 = (const float*)d_in[1];
    const float* Mu1 = (const float*)d_in[2];
    const float* S0  = (const float*)d_in[3];
    const float* S1  = (const float*)d_in[4];
    const float* Lam = (const float*)d_in[5];
    const float* tp  = (const float*)d_in[6];
    const float* ep  = (const float*)d_in[7];
    float* out = (float*)d_out;

    cudaFuncSetAttribute(fused_mma, cudaFuncAttributeMaxDynamicSharedMemorySize, DYN_SMEM);

    void* uacc_ptr = nullptr;
    void* nacc_ptr = nullptr;
    cudaGetSymbolAddress(&uacc_ptr, g_uacc);
    cudaGetSymbolAddress(&nacc_ptr, g_nacc);
    cudaMemsetAsync(uacc_ptr, 0, (size_t)B_SZ * KDIM * sizeof(float));
    cudaMemsetAsync(nacc_ptr, 0, B_SZ * sizeof(float));

    fused_mma<<<dim3(8, 16), 512, DYN_SMEM>>>(X, Mu0, Mu1, S0, S1, Lam, tp, ep);
    finalize<<<(B_SZ * D_SZ) / 256, 256>>>(X, out);
}